// round 12
// baseline (speedup 1.0000x reference)
#include <cuda_runtime.h>
#include <cstdint>

#define B_  4
#define N_  2048
#define D_  128

// smem layout (bytes)
#define SM_SQI 0
#define SM_SQJ 1024
#define SM_A   4096
#define SM_B   (4096 + 131072)
#define SM_TOTAL (4096 + 131072 + 65536)

__device__ float g_sq[B_ * N_];
// pre-swizzled tiles: [b*16 + tile][row 0..127][512 bytes]
__device__ __align__(16) char g_xs[B_ * 16 * 128 * 512];

// preprocess: per row, compute squared norm AND write pair-interleaved swizzled layout
// slot s = 4*kbi + c holds (x[8*kbi+c], x[8*kbi+c+4]); phys = s ^ ((r&3)<<2)
__global__ void prep_kernel(const float* __restrict__ x) {
    int wid = threadIdx.x >> 5, lane = threadIdx.x & 31;
    int row = blockIdx.x * 8 + wid;          // 0 .. B_*N_-1
    float4 v = *(const float4*)(x + (size_t)row * D_ + lane * 4);

    float s = v.x * v.x + v.y * v.y + v.z * v.z + v.w * v.w;
#pragma unroll
    for (int o = 16; o > 0; o >>= 1) s += __shfl_xor_sync(0xffffffffu, s, o);
    if (lane == 0) g_sq[row] = s;

    float4 u;
    u.x = __shfl_xor_sync(0xffffffffu, v.x, 1);
    u.y = __shfl_xor_sync(0xffffffffu, v.y, 1);
    u.z = __shfl_xor_sync(0xffffffffu, v.z, 1);
    u.w = __shfl_xor_sync(0xffffffffu, v.w, 1);

    const int r = row & 127;
    const int x4 = (r & 3) << 2;
    char* rowS = g_xs + (size_t)(row >> 7) * 65536 + r * 512;
    const int kbi = lane >> 1;
    if ((lane & 1) == 0) {
        *(float2*)(rowS + ((4 * kbi + 0) ^ x4) * 8) = make_float2(v.x, u.x);
        *(float2*)(rowS + ((4 * kbi + 1) ^ x4) * 8) = make_float2(v.y, u.y);
    } else {
        *(float2*)(rowS + ((4 * kbi + 2) ^ x4) * 8) = make_float2(u.z, v.z);
        *(float2*)(rowS + ((4 * kbi + 3) ^ x4) * 8) = make_float2(u.w, v.w);
    }
}

__device__ __forceinline__ float fsqrt_approx(float a) {
    float r;
    asm("sqrt.approx.f32 %0, %1;" : "=f"(r) : "f"(a));
    return r;
}

__device__ __forceinline__ void cp16(uint32_t s, const char* g) {
    asm volatile("cp.async.cg.shared.global [%0], [%1], 16;" :: "r"(s), "l"(g));
}

// copy one 64KB pre-swizzled tile global->smem via cp.async (512 threads)
__device__ __forceinline__ void tile_cp(uint32_t sdst, const char* gsrc, int tid) {
#pragma unroll
    for (int i = 0; i < 8; i++)
        cp16(sdst + tid * 16 + i * 8192, gsrc + tid * 16 + i * 8192);
}

__global__ __launch_bounds__(512, 1) void edm_mma_kernel(float* __restrict__ out) {
    extern __shared__ char smem[];
    const uint32_t smem_b = (uint32_t)__cvta_generic_to_shared(smem);
    const int tid = threadIdx.x;
    const int wid = tid >> 5;
    const int lane = tid & 31;
    const int g  = lane >> 2;   // 0..7
    const int cc = lane & 3;    // 0..3

    const int q    = blockIdx.x;             // j-quarter 0..3
    const int slab = blockIdx.y;             // 0..7
    const int b    = blockIdx.z;
    const int i0   = slab * 256;
    const int jbase = q * 512;
    const char* xs_b = g_xs + (size_t)b * 16 * 65536;

    // ---- prologue: A slab (2 tiles = 128KB) + B tile 0 via cp.async ----
    tile_cp(smem_b + SM_A, xs_b + (size_t)(2 * slab) * 65536, tid);
    tile_cp(smem_b + SM_A + 65536, xs_b + (size_t)(2 * slab + 1) * 65536, tid);
    tile_cp(smem_b + SM_B, xs_b + (size_t)(q * 4) * 65536, tid);
    asm volatile("cp.async.commit_group;");
    if (tid < 256) ((float*)(smem + SM_SQI))[tid] = g_sq[b * N_ + i0 + tid];
    ((float*)(smem + SM_SQJ))[tid] = g_sq[b * N_ + jbase + tid];
    asm volatile("cp.async.wait_group 0;");
    __syncthreads();

    const int wm = (wid & 3) * 64;    // 0,64,128,192
    const int wn = (wid >> 2) * 32;   // 0,32,64,96
    const int gx4 = (g & 3) << 2;
    const float* sqi_s = (const float*)(smem + SM_SQI);
    const float* sqj_s = (const float*)(smem + SM_SQJ);

#pragma unroll 1
    for (int jj = 0; jj < 4; jj++) {
        // ---- mainloop: warp tile 64x32, m16n8k8 tf32 ----
        float acc[4][4][4];
#pragma unroll
        for (int mt = 0; mt < 4; mt++)
#pragma unroll
            for (int nt = 0; nt < 4; nt++)
#pragma unroll
                for (int e = 0; e < 4; e++) acc[mt][nt][e] = 0.f;

#pragma unroll
        for (int kst = 0; kst < 16; kst++) {
            const int phys = (4 * kst + cc) ^ gx4;
            uint32_t a[4][4], bf[4][2];
#pragma unroll
            for (int nt = 0; nt < 4; nt++) {
                int n0 = wn + 8 * nt + g;
                float2 b01 = *(float2*)(smem + SM_B + n0 * 512 + phys * 8);
                bf[nt][0] = __float_as_uint(b01.x);
                bf[nt][1] = __float_as_uint(b01.y);
            }
#pragma unroll
            for (int mt = 0; mt < 4; mt++) {
                int r0 = wm + 16 * mt + g;
                float2 a02 = *(float2*)(smem + SM_A + r0 * 512 + phys * 8);
                float2 a13 = *(float2*)(smem + SM_A + (r0 + 8) * 512 + phys * 8);
                a[mt][0] = __float_as_uint(a02.x);
                a[mt][1] = __float_as_uint(a13.x);
                a[mt][2] = __float_as_uint(a02.y);
                a[mt][3] = __float_as_uint(a13.y);
            }
#pragma unroll
            for (int mt = 0; mt < 4; mt++)
#pragma unroll
                for (int nt = 0; nt < 4; nt++) {
                    asm volatile(
                        "mma.sync.aligned.m16n8k8.row.col.f32.tf32.tf32.f32 "
                        "{%0,%1,%2,%3}, {%4,%5,%6,%7}, {%8,%9}, {%0,%1,%2,%3};"
                        : "+f"(acc[mt][nt][0]), "+f"(acc[mt][nt][1]),
                          "+f"(acc[mt][nt][2]), "+f"(acc[mt][nt][3])
                        : "r"(a[mt][0]), "r"(a[mt][1]), "r"(a[mt][2]), "r"(a[mt][3]),
                          "r"(bf[nt][0]), "r"(bf[nt][1]));
                }
        }

        // all warps done reading B -> start next B copy, hidden by epilogue
        __syncthreads();
        if (jj < 3) {
            tile_cp(smem_b + SM_B, xs_b + (size_t)(q * 4 + jj + 1) * 65536, tid);
            asm volatile("cp.async.commit_group;");
        }

        // ---- epilogue: d = sqrt(max(sqi + sqj - 2*dot, 0) + eps) ----
        {
            float2 sqj2[4];
            const int sjb = jj * 128 + wn;
#pragma unroll
            for (int nt = 0; nt < 4; nt++)
                sqj2[nt] = *(const float2*)&sqj_s[sjb + 8 * nt + 2 * cc];
#pragma unroll
            for (int mt = 0; mt < 4; mt++) {
#pragma unroll
                for (int h = 0; h < 2; h++) {
                    int row = wm + 16 * mt + 8 * h + g;
                    float si = sqi_s[row];
                    float* orow = out + ((size_t)(b * N_ + i0 + row)) * N_ +
                                  jbase + jj * 128 + wn;
#pragma unroll
                    for (int nt = 0; nt < 4; nt++) {
                        float d0 = acc[mt][nt][2 * h];
                        float d1 = acc[mt][nt][2 * h + 1];
                        float v0 = fsqrt_approx(fmaxf(fmaf(-2.f, d0, si + sqj2[nt].x), 0.f) + 1e-7f);
                        float v1 = fsqrt_approx(fmaxf(fmaf(-2.f, d1, si + sqj2[nt].y), 0.f) + 1e-7f);
                        *(float2*)(orow + 8 * nt + 2 * cc) = make_float2(v0, v1);
                    }
                }
            }
        }

        if (jj < 3) {
            asm volatile("cp.async.wait_group 0;");
            __syncthreads();
        }
    }
}

extern "C" void kernel_launch(void* const* d_in, const int* in_sizes, int n_in,
                              void* d_out, int out_size) {
    const float* x = (const float*)d_in[0];
    float* out = (float*)d_out;

    prep_kernel<<<B_ * N_ / 8, 256>>>(x);

    cudaFuncSetAttribute(edm_mma_kernel, cudaFuncAttributeMaxDynamicSharedMemorySize, SM_TOTAL);
    dim3 grid(4, 8, B_);
    edm_mma_kernel<<<grid, 512, SM_TOTAL>>>(out);
}

// round 13
// speedup vs baseline: 1.3403x; 1.3403x over previous
#include <cuda_runtime.h>
#include <cuda_fp16.h>
#include <cstdint>

#define B_  4
#define N_  2048
#define D_  128

// smem layout (bytes)
#define SM_SQI 0
#define SM_SQJ 1024
#define SM_A   4096
#define SM_B   (4096 + 65536)
#define SM_TOTAL (4096 + 65536 + 32768)

__device__ float g_sq[B_ * N_];
// pre-swizzled fp16 tiles: [b*16 + tile][row 0..127][256 bytes]
__device__ __align__(16) char g_xs[B_ * 16 * 128 * 256];

__device__ __forceinline__ uint32_t pkh2(float a, float b) {
    __half2 h = __floats2half2_rn(a, b);
    return *(uint32_t*)&h;
}

// preprocess: per row, squared norm + fp16 pair-interleaved swizzled layout
// half2 pair p = (x[2p], x[2p+1]); slot s = 4*kg + c holds (pair 8kg+c, pair 8kg+c+4)
// phys = s ^ ((r&3)<<2); row stride 256 bytes (32 slots x 8B)
__global__ void prep_kernel(const float* __restrict__ x) {
    int wid = threadIdx.x >> 5, lane = threadIdx.x & 31;
    int row = blockIdx.x * 8 + wid;          // 0 .. B_*N_-1
    float4 v = *(const float4*)(x + (size_t)row * D_ + lane * 4);

    float s = v.x * v.x + v.y * v.y + v.z * v.z + v.w * v.w;
#pragma unroll
    for (int o = 16; o > 0; o >>= 1) s += __shfl_xor_sync(0xffffffffu, s, o);
    if (lane == 0) g_sq[row] = s;

    float4 u;
    u.x = __shfl_xor_sync(0xffffffffu, v.x, 2);
    u.y = __shfl_xor_sync(0xffffffffu, v.y, 2);
    u.z = __shfl_xor_sync(0xffffffffu, v.z, 2);
    u.w = __shfl_xor_sync(0xffffffffu, v.w, 2);

    if ((lane & 2) == 0) {
        const int r = row & 127;
        const int x4 = (r & 3) << 2;
        char* rowS = g_xs + (size_t)(row >> 7) * 32768 + r * 256;
        const int kg = lane >> 2;
        const int c0 = (2 * lane) & 7;       // 0 or 2
        uint2 w0, w1;
        w0.x = pkh2(v.x, v.y); w0.y = pkh2(u.x, u.y);   // pair 2*lane, partner +4
        w1.x = pkh2(v.z, v.w); w1.y = pkh2(u.z, u.w);   // pair 2*lane+1, partner +4
        *(uint2*)(rowS + ((4 * kg + c0) ^ x4) * 8)     = w0;
        *(uint2*)(rowS + ((4 * kg + c0 + 1) ^ x4) * 8) = w1;
    }
}

__device__ __forceinline__ float fsqrt_approx(float a) {
    float r;
    asm("sqrt.approx.f32 %0, %1;" : "=f"(r) : "f"(a));
    return r;
}

__device__ __forceinline__ void cp16(uint32_t s, const char* g) {
    asm volatile("cp.async.cg.shared.global [%0], [%1], 16;" :: "r"(s), "l"(g));
}

// copy pre-swizzled fp16 data global->smem via cp.async (512 threads)
__device__ __forceinline__ void cp32k(uint32_t sdst, const char* gsrc, int tid) {
#pragma unroll
    for (int i = 0; i < 4; i++)
        cp16(sdst + tid * 16 + i * 8192, gsrc + tid * 16 + i * 8192);
}
__device__ __forceinline__ void cp64k(uint32_t sdst, const char* gsrc, int tid) {
#pragma unroll
    for (int i = 0; i < 8; i++)
        cp16(sdst + tid * 16 + i * 8192, gsrc + tid * 16 + i * 8192);
}

__global__ __launch_bounds__(512, 1) void edm_mma_kernel(float* __restrict__ out) {
    extern __shared__ char smem[];
    const uint32_t smem_b = (uint32_t)__cvta_generic_to_shared(smem);
    const int tid = threadIdx.x;
    const int wid = tid >> 5;
    const int lane = tid & 31;
    const int g  = lane >> 2;   // 0..7
    const int cc = lane & 3;    // 0..3

    const int q    = blockIdx.x;             // j-quarter 0..3
    const int slab = blockIdx.y;             // 0..7
    const int b    = blockIdx.z;
    const int i0   = slab * 256;
    const int jbase = q * 512;
    const char* xs_b = g_xs + (size_t)b * 16 * 32768;

    // ---- prologue: A slab (256 rows = 64KB) + B tile 0 (32KB) via cp.async ----
    cp64k(smem_b + SM_A, xs_b + (size_t)(2 * slab) * 32768, tid);
    cp32k(smem_b + SM_B, xs_b + (size_t)(q * 4) * 32768, tid);
    asm volatile("cp.async.commit_group;");
    if (tid < 256) ((float*)(smem + SM_SQI))[tid] = g_sq[b * N_ + i0 + tid];
    ((float*)(smem + SM_SQJ))[tid] = g_sq[b * N_ + jbase + tid];
    asm volatile("cp.async.wait_group 0;");
    __syncthreads();

    const int wm = (wid & 3) * 64;    // 0,64,128,192
    const int wn = (wid >> 2) * 32;   // 0,32,64,96
    const int gx4 = (g & 3) << 2;
    const float* sqi_s = (const float*)(smem + SM_SQI);
    const float* sqj_s = (const float*)(smem + SM_SQJ);

#pragma unroll 1
    for (int jj = 0; jj < 4; jj++) {
        // ---- mainloop: warp tile 64x32, m16n8k16 fp16, 8 k-steps ----
        float acc[4][4][4];
#pragma unroll
        for (int mt = 0; mt < 4; mt++)
#pragma unroll
            for (int nt = 0; nt < 4; nt++)
#pragma unroll
                for (int e = 0; e < 4; e++) acc[mt][nt][e] = 0.f;

#pragma unroll
        for (int kst = 0; kst < 8; kst++) {
            const int phys = (4 * kst + cc) ^ gx4;
            uint32_t a[4][4], bf[4][2];
#pragma unroll
            for (int nt = 0; nt < 4; nt++) {
                int n0 = wn + 8 * nt + g;
                uint2 b01 = *(uint2*)(smem + SM_B + n0 * 256 + phys * 8);
                bf[nt][0] = b01.x;
                bf[nt][1] = b01.y;
            }
#pragma unroll
            for (int mt = 0; mt < 4; mt++) {
                int r0 = wm + 16 * mt + g;
                uint2 a02 = *(uint2*)(smem + SM_A + r0 * 256 + phys * 8);
                uint2 a13 = *(uint2*)(smem + SM_A + (r0 + 8) * 256 + phys * 8);
                a[mt][0] = a02.x;
                a[mt][1] = a13.x;
                a[mt][2] = a02.y;
                a[mt][3] = a13.y;
            }
#pragma unroll
            for (int mt = 0; mt < 4; mt++)
#pragma unroll
                for (int nt = 0; nt < 4; nt++) {
                    asm volatile(
                        "mma.sync.aligned.m16n8k16.row.col.f32.f16.f16.f32 "
                        "{%0,%1,%2,%3}, {%4,%5,%6,%7}, {%8,%9}, {%0,%1,%2,%3};"
                        : "+f"(acc[mt][nt][0]), "+f"(acc[mt][nt][1]),
                          "+f"(acc[mt][nt][2]), "+f"(acc[mt][nt][3])
                        : "r"(a[mt][0]), "r"(a[mt][1]), "r"(a[mt][2]), "r"(a[mt][3]),
                          "r"(bf[nt][0]), "r"(bf[nt][1]));
                }
        }

        // all warps done reading B -> start next B copy, hidden by epilogue
        __syncthreads();
        if (jj < 3) {
            cp32k(smem_b + SM_B, xs_b + (size_t)(q * 4 + jj + 1) * 32768, tid);
            asm volatile("cp.async.commit_group;");
        }

        // ---- epilogue: d = sqrt(max(sqi + sqj - 2*dot, 0) + eps) ----
        {
            float2 sqj2[4];
            const int sjb = jj * 128 + wn;
#pragma unroll
            for (int nt = 0; nt < 4; nt++)
                sqj2[nt] = *(const float2*)&sqj_s[sjb + 8 * nt + 2 * cc];
#pragma unroll
            for (int mt = 0; mt < 4; mt++) {
#pragma unroll
                for (int h = 0; h < 2; h++) {
                    int row = wm + 16 * mt + 8 * h + g;
                    float si = sqi_s[row];
                    float* orow = out + ((size_t)(b * N_ + i0 + row)) * N_ +
                                  jbase + jj * 128 + wn;
#pragma unroll
                    for (int nt = 0; nt < 4; nt++) {
                        float d0 = acc[mt][nt][2 * h];
                        float d1 = acc[mt][nt][2 * h + 1];
                        float v0 = fsqrt_approx(fmaxf(fmaf(-2.f, d0, si + sqj2[nt].x), 0.f) + 1e-7f);
                        float v1 = fsqrt_approx(fmaxf(fmaf(-2.f, d1, si + sqj2[nt].y), 0.f) + 1e-7f);
                        *(float2*)(orow + 8 * nt + 2 * cc) = make_float2(v0, v1);
                    }
                }
            }
        }

        if (jj < 3) {
            asm volatile("cp.async.wait_group 0;");
            __syncthreads();
        }
    }
}

extern "C" void kernel_launch(void* const* d_in, const int* in_sizes, int n_in,
                              void* d_out, int out_size) {
    const float* x = (const float*)d_in[0];
    float* out = (float*)d_out;

    prep_kernel<<<B_ * N_ / 8, 256>>>(x);

    cudaFuncSetAttribute(edm_mma_kernel, cudaFuncAttributeMaxDynamicSharedMemorySize, SM_TOTAL);
    dim3 grid(4, 8, B_);
    edm_mma_kernel<<<grid, 512, SM_TOTAL>>>(out);
}

// round 14
// speedup vs baseline: 1.3830x; 1.0318x over previous
#include <cuda_runtime.h>
#include <cuda_fp16.h>
#include <cstdint>

#define B_  4
#define N_  2048
#define D_  128
#define GRID 148
#define UNITS 1024   // 4 b * 16 slabs * 16 j-tiles (each 128x128)

// smem layout (bytes): A0,A1,B0,B1 tiles of 32KB
#define SM_A0 0
#define SM_A1 32768
#define SM_B0 65536
#define SM_B1 98304
#define SM_TOTAL 131072

__device__ float g_sq[B_ * N_];
// pre-swizzled fp16 tiles: [b*16 + tile][row 0..127][256 bytes]
__device__ __align__(16) char g_xs[B_ * 16 * 128 * 256];

__device__ __forceinline__ uint32_t pkh2(float a, float b) {
    __half2 h = __floats2half2_rn(a, b);
    return *(uint32_t*)&h;
}

// preprocess: per row, squared norm + fp16 pair-interleaved swizzled layout
// half2 pair p = (x[2p], x[2p+1]); slot s = 4*kg + c holds (pair 8kg+c, pair 8kg+c+4)
// phys = s ^ ((r&3)<<2); row stride 256 bytes (32 slots x 8B)
__global__ void prep_kernel(const float* __restrict__ x) {
    int wid = threadIdx.x >> 5, lane = threadIdx.x & 31;
    int row = blockIdx.x * 8 + wid;          // 0 .. B_*N_-1
    float4 v = *(const float4*)(x + (size_t)row * D_ + lane * 4);

    float s = v.x * v.x + v.y * v.y + v.z * v.z + v.w * v.w;
#pragma unroll
    for (int o = 16; o > 0; o >>= 1) s += __shfl_xor_sync(0xffffffffu, s, o);
    if (lane == 0) g_sq[row] = s;

    float4 u;
    u.x = __shfl_xor_sync(0xffffffffu, v.x, 2);
    u.y = __shfl_xor_sync(0xffffffffu, v.y, 2);
    u.z = __shfl_xor_sync(0xffffffffu, v.z, 2);
    u.w = __shfl_xor_sync(0xffffffffu, v.w, 2);

    if ((lane & 2) == 0) {
        const int r = row & 127;
        const int x4 = (r & 3) << 2;
        char* rowS = g_xs + (size_t)(row >> 7) * 32768 + r * 256;
        const int kg = lane >> 2;
        const int c0 = (2 * lane) & 7;       // 0 or 2
        uint2 w0, w1;
        w0.x = pkh2(v.x, v.y); w0.y = pkh2(u.x, u.y);
        w1.x = pkh2(v.z, v.w); w1.y = pkh2(u.z, u.w);
        *(uint2*)(rowS + ((4 * kg + c0) ^ x4) * 8)     = w0;
        *(uint2*)(rowS + ((4 * kg + c0 + 1) ^ x4) * 8) = w1;
    }
}

__device__ __forceinline__ float fsqrt_approx(float a) {
    float r;
    asm("sqrt.approx.f32 %0, %1;" : "=f"(r) : "f"(a));
    return r;
}

__device__ __forceinline__ void cp16(uint32_t s, const char* g) {
    asm volatile("cp.async.cg.shared.global [%0], [%1], 16;" :: "r"(s), "l"(g));
}

// copy one 32KB pre-swizzled tile global->smem via cp.async (256 threads)
__device__ __forceinline__ void cp32k(uint32_t sdst, const char* gsrc, int tid) {
#pragma unroll
    for (int i = 0; i < 8; i++)
        cp16(sdst + tid * 16 + i * 4096, gsrc + tid * 16 + i * 4096);
}

__global__ __launch_bounds__(256, 1) void edm_mma_kernel(float* __restrict__ out) {
    extern __shared__ char smem[];
    const uint32_t smem_b = (uint32_t)__cvta_generic_to_shared(smem);
    const int tid = threadIdx.x;
    const int wid = tid >> 5;
    const int lane = tid & 31;
    const int g  = lane >> 2;   // 0..7
    const int cc = lane & 3;    // 0..3

    const int wm = (wid & 1) * 64;    // 0,64
    const int wn = (wid >> 1) * 32;   // 0,32,64,96
    const int gx4 = (g & 3) << 2;

    const int us = (UNITS * blockIdx.x) / GRID;
    const int ue = (UNITS * (blockIdx.x + 1)) / GRID;

    // ---- prologue: load unit us's A slab + B tile ----
    {
        const int u = us;
        const int key = u >> 4;          // b*16 + slab
        const int b = u >> 8, jt = u & 15;
        cp32k(smem_b + SM_A0, g_xs + (size_t)key * 32768, tid);
        cp32k(smem_b + SM_B0, g_xs + (size_t)((b << 4) + jt) * 32768, tid);
        asm volatile("cp.async.commit_group;");
        asm volatile("cp.async.wait_group 0;");
    }
    __syncthreads();

    int pa = 0, pb = 0;

#pragma unroll 1
    for (int u = us; u < ue; u++) {
        const int key = u >> 4;
        const int b = u >> 8;
        const int slab = (u >> 4) & 15;
        const int jt = u & 15;
        const bool havenext = (u + 1 < ue);
        bool akey = false;

        // prefetch next unit's tiles (flows during mainloop)
        if (havenext) {
            const int u2 = u + 1;
            const int key2 = u2 >> 4, b2 = u2 >> 8, jt2 = u2 & 15;
            cp32k(smem_b + (pb ? SM_B0 : SM_B1),
                  g_xs + (size_t)((b2 << 4) + jt2) * 32768, tid);
            akey = (key2 != key);
            if (akey)
                cp32k(smem_b + (pa ? SM_A0 : SM_A1), g_xs + (size_t)key2 * 32768, tid);
            asm volatile("cp.async.commit_group;");
        }

        const char* As = smem + (pa ? SM_A1 : SM_A0);
        const char* Bs = smem + (pb ? SM_B1 : SM_B0);

        // sq prefetch (L2-hot)
        const float* sqb = g_sq + b * N_;
        float si_[2][2];
        float2 sqj2[4];
#pragma unroll
        for (int mt = 0; mt < 2; mt++)
#pragma unroll
            for (int h = 0; h < 2; h++)
                si_[mt][h] = sqb[slab * 128 + wm + 32 * mt + 8 * h + g];
        // note: mt here indexes 0/1 for rows wm+{0,32}; full set loaded below per 16-row tile
        float si4[4][2];
#pragma unroll
        for (int mt = 0; mt < 4; mt++)
#pragma unroll
            for (int h = 0; h < 2; h++)
                si4[mt][h] = sqb[slab * 128 + wm + 16 * mt + 8 * h + g];
#pragma unroll
        for (int nt = 0; nt < 4; nt++)
            sqj2[nt] = *(const float2*)&sqb[jt * 128 + wn + 8 * nt + 2 * cc];
        (void)si_;

        // ---- mainloop: warp tile 64x32, m16n8k16 fp16, frag double-buffered ----
        float acc[4][4][4];
#pragma unroll
        for (int mt = 0; mt < 4; mt++)
#pragma unroll
            for (int nt = 0; nt < 4; nt++)
#pragma unroll
                for (int e = 0; e < 4; e++) acc[mt][nt][e] = 0.f;

        uint32_t a[2][4][4], bf[2][4][2];
        {
            const int phys = cc ^ gx4;
#pragma unroll
            for (int mt = 0; mt < 4; mt++) {
                int r0 = wm + 16 * mt + g;
                uint2 a02 = *(uint2*)(As + r0 * 256 + phys * 8);
                uint2 a13 = *(uint2*)(As + (r0 + 8) * 256 + phys * 8);
                a[0][mt][0] = a02.x; a[0][mt][1] = a13.x;
                a[0][mt][2] = a02.y; a[0][mt][3] = a13.y;
            }
#pragma unroll
            for (int nt = 0; nt < 4; nt++) {
                int n0 = wn + 8 * nt + g;
                uint2 b01 = *(uint2*)(Bs + n0 * 256 + phys * 8);
                bf[0][nt][0] = b01.x; bf[0][nt][1] = b01.y;
            }
        }

#pragma unroll
        for (int kst = 0; kst < 8; kst++) {
            const int cur = kst & 1, nxt = cur ^ 1;
            if (kst < 7) {
                const int phys = (4 * (kst + 1) + cc) ^ gx4;
#pragma unroll
                for (int mt = 0; mt < 4; mt++) {
                    int r0 = wm + 16 * mt + g;
                    uint2 a02 = *(uint2*)(As + r0 * 256 + phys * 8);
                    uint2 a13 = *(uint2*)(As + (r0 + 8) * 256 + phys * 8);
                    a[nxt][mt][0] = a02.x; a[nxt][mt][1] = a13.x;
                    a[nxt][mt][2] = a02.y; a[nxt][mt][3] = a13.y;
                }
#pragma unroll
                for (int nt = 0; nt < 4; nt++) {
                    int n0 = wn + 8 * nt + g;
                    uint2 b01 = *(uint2*)(Bs + n0 * 256 + phys * 8);
                    bf[nxt][nt][0] = b01.x; bf[nxt][nt][1] = b01.y;
                }
            }
#pragma unroll
            for (int mt = 0; mt < 4; mt++)
#pragma unroll
                for (int nt = 0; nt < 4; nt++) {
                    asm volatile(
                        "mma.sync.aligned.m16n8k16.row.col.f32.f16.f16.f32 "
                        "{%0,%1,%2,%3}, {%4,%5,%6,%7}, {%8,%9}, {%0,%1,%2,%3};"
                        : "+f"(acc[mt][nt][0]), "+f"(acc[mt][nt][1]),
                          "+f"(acc[mt][nt][2]), "+f"(acc[mt][nt][3])
                        : "r"(a[cur][mt][0]), "r"(a[cur][mt][1]),
                          "r"(a[cur][mt][2]), "r"(a[cur][mt][3]),
                          "r"(bf[cur][nt][0]), "r"(bf[cur][nt][1]));
                }
        }

        // ---- epilogue: d = sqrt(max(sqi + sqj - 2*dot, 0) + eps) ----
#pragma unroll
        for (int mt = 0; mt < 4; mt++) {
#pragma unroll
            for (int h = 0; h < 2; h++) {
                int row = wm + 16 * mt + 8 * h + g;
                float si = si4[mt][h];
                float* orow = out + ((size_t)(b * N_ + slab * 128 + row)) * N_ +
                              jt * 128 + wn;
#pragma unroll
                for (int nt = 0; nt < 4; nt++) {
                    float d0 = acc[mt][nt][2 * h];
                    float d1 = acc[mt][nt][2 * h + 1];
                    float v0 = fsqrt_approx(fmaxf(fmaf(-2.f, d0, si + sqj2[nt].x), 0.f) + 1e-7f);
                    float v1 = fsqrt_approx(fmaxf(fmaf(-2.f, d1, si + sqj2[nt].y), 0.f) + 1e-7f);
                    *(float2*)(orow + 8 * nt + 2 * cc) = make_float2(v0, v1);
                }
            }
        }

        if (havenext) {
            asm volatile("cp.async.wait_group 0;");
            __syncthreads();
            pb ^= 1;
            if (akey) pa ^= 1;
        }
    }
}

extern "C" void kernel_launch(void* const* d_in, const int* in_sizes, int n_in,
                              void* d_out, int out_size) {
    const float* x = (const float*)d_in[0];
    float* out = (float*)d_out;

    prep_kernel<<<B_ * N_ / 8, 256>>>(x);

    cudaFuncSetAttribute(edm_mma_kernel, cudaFuncAttributeMaxDynamicSharedMemorySize, SM_TOTAL);
    edm_mma_kernel<<<GRID, 256, SM_TOTAL>>>(out);
}